// round 5
// baseline (speedup 1.0000x reference)
#include <cuda_runtime.h>
#include <cstdint>

#define NG        1024
#define NB        592            // blocks: exactly one wave (148 SM x 4)
#define NT        512
#define ITERS     30
#define FIXSCALE  1048576.0f     // 2^20 fixed point for S0
#define INVSCALE  (1.0f / 1048576.0f)
#define CNT_SHIFT 44

typedef unsigned long long ull;

// ---------------- device scratch (no allocations allowed) ----------------
__device__ ull   g_part[NG * NB];       // per-block partial hist, g_part[g*NB + b]
__device__ float g_alphas[NG];
__device__ unsigned g_cnt0, g_flag0;    // grid barrier 0 (zero-init .bss)
__device__ unsigned g_cnt1, g_flag1;    // grid barrier 1

// Monotonic-generation grid barrier. Safe across graph replays:
// cnt self-resets, flag only ever increments. Requires all NB blocks resident
// (guaranteed: 592 blocks = 148 SMs x 4, 512 thr, <=32 regs via launch_bounds).
__device__ __forceinline__ void grid_barrier(unsigned* cnt, unsigned* flag, int tid) {
    __syncthreads();
    if (tid == 0) {
        __threadfence();                       // publish my writes
        unsigned gen = atomicAdd(flag, 0u);    // read generation BEFORE arriving
        if (atomicAdd(cnt, 1u) == NB - 1u) {
            *cnt = 0u;
            __threadfence();
            atomicAdd(flag, 1u);               // release everyone
        } else {
            while (atomicAdd(flag, 0u) == gen) __nanosleep(200);
        }
    }
    __syncthreads();
}

__device__ __forceinline__ void hist_one(ull* acc, float a, float b, int g) {
    float yr = fmaxf(b, 1e-9f);
    float r  = __fdividef(a, yr);
    float s  = fminf(fmaxf(r, 0.9f), 1.1f);
    ull v = (ull)(unsigned)(s * FIXSCALE) + (1ull << CNT_SHIFT);
    atomicAdd(&acc[g], v);
}

__device__ __forceinline__ float out_one(float a, float b, int g) {
    float yr = fmaxf(b, 1e-9f);
    float alpha = __ldg(&g_alphas[g]);
    float v = fmaf(alpha, yr, a);              // == a exactly when alpha == 0
    return fminf(fmaxf(v, 0.9f * yr), 1.1f * yr);
}

__global__ void __launch_bounds__(NT, 4) k_fused(
        const float4* __restrict__ yraw4, const float4* __restrict__ yreal4,
        const int4* __restrict__ gid4, float4* __restrict__ out4, int n4,
        const float* __restrict__ yraw, const float* __restrict__ yreal,
        const int* __restrict__ gid, float* __restrict__ out, int n) {
    __shared__ ull acc[NG];                    // hist, then reduce scratch
    __shared__ float sf[NT];                   // fallback scratch
    const int tid = threadIdx.x;
    const int bid = blockIdx.x;
    const int stride = NB * NT;
    const int base4 = bid * NT + tid;

    // ================= phase 1: per-block fixed-point histogram =================
    for (int i = tid; i < NG; i += NT) acc[i] = 0ull;
    __syncthreads();

    #pragma unroll 2
    for (int i = base4; i < n4; i += stride) {
        float4 a = yraw4[i];
        float4 b = yreal4[i];
        int4   g = gid4[i];
        hist_one(acc, a.x, b.x, g.x);
        hist_one(acc, a.y, b.y, g.y);
        hist_one(acc, a.z, b.z, g.z);
        hist_one(acc, a.w, b.w, g.w);
    }
    {   // tail (n not multiple of 4)
        int t = base4, tb = n4 * 4;
        if (t < n - tb) hist_one(acc, yraw[tb + t], yreal[tb + t], gid[tb + t]);
    }
    __syncthreads();
    for (int i = tid; i < NG; i += NT)
        g_part[i * NB + bid] = acc[i];

    grid_barrier(&g_cnt0, &g_flag0, tid);

    // ====== phase 2: reduce partials, feasibility, (rare) bisect fallback ======
    // block b owns groups b and b+NB
    for (int g = bid; g < NG; g += NB) {
        ull v = 0ull;
        for (int b = tid; b < NB; b += NT) v += g_part[g * NB + b];
        acc[tid] = v;
        __syncthreads();
        for (int d = NT / 2; d > 0; d >>= 1) {
            if (tid < d) acc[tid] += acc[tid + d];
            __syncthreads();
        }
        __shared__ int   s_infeas;
        __shared__ float s_T;
        if (tid == 0) {
            ull a   = acc[0];
            int cnt = (int)(a >> CNT_SHIFT);
            float S0 = (float)(a & ((1ull << CNT_SHIFT) - 1ull)) * INVSCALE;
            float fn = (float)cnt;
            float L = 0.95f * fn, U = 1.05f * fn;
            bool infeas = (cnt > 0) && (S0 < L || S0 > U);
            s_infeas = infeas ? 1 : 0;
            s_T = (S0 < L) ? L : U;
            g_alphas[g] = 0.0f;
        }
        __syncthreads();
        if (!s_infeas) continue;   // fast path (always, for this input)

        // correctness-only fallback: brute-force bisection over full arrays
        float rmn = __int_as_float(0x7f800000);
        float rmx = __int_as_float(0xff800000);
        for (int i = tid; i < n; i += NT) {
            if (gid[i] == g) {
                float yr = fmaxf(yreal[i], 1e-9f);
                float r  = yraw[i] / yr;
                rmn = fminf(rmn, r);
                rmx = fmaxf(rmx, r);
            }
        }
        sf[tid] = rmn; __syncthreads();
        for (int d = NT / 2; d > 0; d >>= 1) { if (tid < d) sf[tid] = fminf(sf[tid], sf[tid + d]); __syncthreads(); }
        rmn = sf[0]; __syncthreads();
        sf[tid] = rmx; __syncthreads();
        for (int d = NT / 2; d > 0; d >>= 1) { if (tid < d) sf[tid] = fmaxf(sf[tid], sf[tid + d]); __syncthreads(); }
        rmx = sf[0]; __syncthreads();

        float lo = 0.9f - rmx - 1.0f;
        float hi = 1.1f - rmn + 1.0f;
        float T = s_T;
        float mid = lo;
        for (int it = 0; it < ITERS; ++it) {
            mid = 0.5f * (lo + hi);
            float p = 0.0f;
            for (int i = tid; i < n; i += NT) {
                if (gid[i] == g) {
                    float yr = fmaxf(yreal[i], 1e-9f);
                    float r  = yraw[i] / yr;
                    p += fminf(fmaxf(r + mid, 0.9f), 1.1f);
                }
            }
            sf[tid] = p; __syncthreads();
            for (int d = NT / 2; d > 0; d >>= 1) { if (tid < d) sf[tid] += sf[tid + d]; __syncthreads(); }
            float S = sf[0]; __syncthreads();
            if (S < T) lo = mid; else hi = mid;
        }
        if (tid == 0) g_alphas[g] = mid;
        __syncthreads();
    }

    grid_barrier(&g_cnt1, &g_flag1, tid);

    // ================= phase 3: output (inputs hot in L2) =================
    #pragma unroll 2
    for (int i = base4; i < n4; i += stride) {
        float4 a = yraw4[i];
        float4 b = yreal4[i];
        int4   g = gid4[i];
        float4 o;
        o.x = out_one(a.x, b.x, g.x);
        o.y = out_one(a.y, b.y, g.y);
        o.z = out_one(a.z, b.z, g.z);
        o.w = out_one(a.w, b.w, g.w);
        out4[i] = o;
    }
    {   // tail
        int t = base4, tb = n4 * 4;
        if (t < n - tb) out[tb + t] = out_one(yraw[tb + t], yreal[tb + t], gid[tb + t]);
    }
}

// ---------------- launch ----------------
extern "C" void kernel_launch(void* const* d_in, const int* in_sizes, int n_in,
                              void* d_out, int out_size) {
    const float* yraw  = (const float*)d_in[0];
    const float* yreal = (const float*)d_in[1];
    const int*   gid   = (const int*)d_in[2];
    float* out = (float*)d_out;
    int n  = in_sizes[0];
    int n4 = n >> 2;

    k_fused<<<NB, NT>>>((const float4*)yraw, (const float4*)yreal, (const int4*)gid,
                        (float4*)d_out, n4, yraw, yreal, gid, out, n);
}

// round 6
// speedup vs baseline: 1.3346x; 1.3346x over previous
#include <cuda_runtime.h>
#include <cstdint>

#define NG        1024
#define NB        592            // blocks: exactly one wave (148 SM x 4)
#define NT        512
#define ITERS     30
#define FIXSCALE  1048576.0f     // 2^20 fixed point for S0
#define INVSCALE  (1.0f / 1048576.0f)
#define CNT_SHIFT 44

typedef unsigned long long ull;

// ---------------- device scratch (no allocations allowed) ----------------
__device__ ull   g_part[NG * NB];       // per-block partial hist, g_part[g*NB + b]
__device__ float g_alphas[NG];
__device__ int   g_any;                 // any infeasible group this replay?
__device__ unsigned g_cnt0, g_flag0;    // grid barrier 0 (zero-init .bss)
__device__ unsigned g_cnt1, g_flag1;    // grid barrier 1

// Monotonic-generation grid barrier. Safe across graph replays:
// cnt self-resets, flag only ever increments. Requires all NB blocks resident
// (guaranteed: 592 blocks = 148 SMs x 4, 512 thr, <=32 regs via launch_bounds).
__device__ __forceinline__ void grid_barrier(unsigned* cnt, unsigned* flag, int tid) {
    __syncthreads();
    if (tid == 0) {
        __threadfence();                       // publish my writes
        unsigned gen = atomicAdd(flag, 0u);    // read generation BEFORE arriving
        if (atomicAdd(cnt, 1u) == NB - 1u) {
            *cnt = 0u;
            __threadfence();
            atomicAdd(flag, 1u);               // release everyone
        } else {
            while (atomicAdd(flag, 0u) == gen) __nanosleep(200);
        }
    }
    __syncthreads();
}

// phase-1 worker: histogram contribution AND fast-path output value
__device__ __forceinline__ float h1(ull* acc, float a, float b, int g) {
    float yr = fmaxf(b, 1e-9f);
    float lo = 0.9f * yr, hi = 1.1f * yr;
    float yc = fminf(fmaxf(a, lo), hi);            // exact reference y_clipped
    float s  = fminf(fmaxf(__fdividef(a, yr), 0.9f), 1.1f);
    atomicAdd(&acc[g], (ull)(unsigned)(s * FIXSCALE) + (1ull << CNT_SHIFT));
    return yc;
}

__device__ __forceinline__ float out_fb(float a, float b, int g) {
    float yr = fmaxf(b, 1e-9f);
    float alpha = __ldg(&g_alphas[g]);
    float v = fmaf(alpha, yr, a);                  // == a exactly when alpha == 0
    return fminf(fmaxf(v, 0.9f * yr), 1.1f * yr);
}

__global__ void __launch_bounds__(NT, 4) k_fused(
        const float4* __restrict__ yraw4, const float4* __restrict__ yreal4,
        const int4* __restrict__ gid4, float4* __restrict__ out4, int n4,
        const float* __restrict__ yraw, const float* __restrict__ yreal,
        const int* __restrict__ gid, float* __restrict__ out, int n) {
    __shared__ ull acc[NG];                    // hist, then reduce scratch
    __shared__ float sf[NT];                   // fallback scratch
    const int tid = threadIdx.x;
    const int bid = blockIdx.x;
    const int stride = NB * NT;
    const int base4 = bid * NT + tid;

    // ====== phase 1: histogram + speculative (feasible-case) output write ======
    for (int i = tid; i < NG; i += NT) acc[i] = 0ull;
    if (bid == 0 && tid == 0) g_any = 0;       // reset flag each replay
    __syncthreads();

    #pragma unroll 2
    for (int i = base4; i < n4; i += stride) {
        float4 a = yraw4[i];
        float4 b = yreal4[i];
        int4   g = gid4[i];
        float4 o;
        o.x = h1(acc, a.x, b.x, g.x);
        o.y = h1(acc, a.y, b.y, g.y);
        o.z = h1(acc, a.z, b.z, g.z);
        o.w = h1(acc, a.w, b.w, g.w);
        out4[i] = o;
    }
    {   // tail (n not multiple of 4)
        int t = base4, tb = n4 * 4;
        if (t < n - tb) out[tb + t] = h1(acc, yraw[tb + t], yreal[tb + t], gid[tb + t]);
    }
    __syncthreads();
    for (int i = tid; i < NG; i += NT)
        g_part[i * NB + bid] = acc[i];

    grid_barrier(&g_cnt0, &g_flag0, tid);

    // ====== phase 2: reduce partials, feasibility, (rare) bisect fallback ======
    for (int g = bid; g < NG; g += NB) {
        ull v = 0ull;
        for (int b = tid; b < NB; b += NT) v += g_part[g * NB + b];
        acc[tid] = v;
        __syncthreads();
        for (int d = NT / 2; d > 0; d >>= 1) {
            if (tid < d) acc[tid] += acc[tid + d];
            __syncthreads();
        }
        __shared__ int   s_infeas;
        __shared__ float s_T;
        if (tid == 0) {
            ull a   = acc[0];
            int cnt = (int)(a >> CNT_SHIFT);
            float S0 = (float)(a & ((1ull << CNT_SHIFT) - 1ull)) * INVSCALE;
            float fn = (float)cnt;
            float L = 0.95f * fn, U = 1.05f * fn;
            bool infeas = (cnt > 0) && (S0 < L || S0 > U);
            s_infeas = infeas ? 1 : 0;
            s_T = (S0 < L) ? L : U;
            g_alphas[g] = 0.0f;
            if (infeas) atomicExch(&g_any, 1);
        }
        __syncthreads();
        if (!s_infeas) continue;   // fast path (always, for this input)

        // correctness-only fallback: brute-force bisection over full arrays
        float rmn = __int_as_float(0x7f800000);
        float rmx = __int_as_float(0xff800000);
        for (int i = tid; i < n; i += NT) {
            if (gid[i] == g) {
                float yr = fmaxf(yreal[i], 1e-9f);
                float r  = yraw[i] / yr;
                rmn = fminf(rmn, r);
                rmx = fmaxf(rmx, r);
            }
        }
        sf[tid] = rmn; __syncthreads();
        for (int d = NT / 2; d > 0; d >>= 1) { if (tid < d) sf[tid] = fminf(sf[tid], sf[tid + d]); __syncthreads(); }
        rmn = sf[0]; __syncthreads();
        sf[tid] = rmx; __syncthreads();
        for (int d = NT / 2; d > 0; d >>= 1) { if (tid < d) sf[tid] = fmaxf(sf[tid], sf[tid + d]); __syncthreads(); }
        rmx = sf[0]; __syncthreads();

        float lo = 0.9f - rmx - 1.0f;
        float hi = 1.1f - rmn + 1.0f;
        float T = s_T;
        float mid = lo;
        for (int it = 0; it < ITERS; ++it) {
            mid = 0.5f * (lo + hi);
            float p = 0.0f;
            for (int i = tid; i < n; i += NT) {
                if (gid[i] == g) {
                    float yr = fmaxf(yreal[i], 1e-9f);
                    float r  = yraw[i] / yr;
                    p += fminf(fmaxf(r + mid, 0.9f), 1.1f);
                }
            }
            sf[tid] = p; __syncthreads();
            for (int d = NT / 2; d > 0; d >>= 1) { if (tid < d) sf[tid] += sf[tid + d]; __syncthreads(); }
            float S = sf[0]; __syncthreads();
            if (S < T) lo = mid; else hi = mid;
        }
        if (tid == 0) g_alphas[g] = mid;
        __syncthreads();
    }

    grid_barrier(&g_cnt1, &g_flag1, tid);

    // ====== phase 3: rewrite pass — ONLY if some group was infeasible ======
    if (g_any) {
        #pragma unroll 2
        for (int i = base4; i < n4; i += stride) {
            float4 a = yraw4[i];
            float4 b = yreal4[i];
            int4   g = gid4[i];
            float4 o;
            o.x = out_fb(a.x, b.x, g.x);
            o.y = out_fb(a.y, b.y, g.y);
            o.z = out_fb(a.z, b.z, g.z);
            o.w = out_fb(a.w, b.w, g.w);
            out4[i] = o;
        }
        int t = base4, tb = n4 * 4;
        if (t < n - tb) out[tb + t] = out_fb(yraw[tb + t], yreal[tb + t], gid[tb + t]);
    }
}

// ---------------- launch ----------------
extern "C" void kernel_launch(void* const* d_in, const int* in_sizes, int n_in,
                              void* d_out, int out_size) {
    const float* yraw  = (const float*)d_in[0];
    const float* yreal = (const float*)d_in[1];
    const int*   gid   = (const int*)d_in[2];
    float* out = (float*)d_out;
    int n  = in_sizes[0];
    int n4 = n >> 2;

    k_fused<<<NB, NT>>>((const float4*)yraw, (const float4*)yreal, (const int4*)gid,
                        (float4*)d_out, n4, yraw, yreal, gid, out, n);
}